// round 3
// baseline (speedup 1.0000x reference)
#include <cuda_runtime.h>
#include <cuda_bf16.h>
#include <cstdint>
#include <cmath>

// ---------------------------------------------------------------------------
// Problem constants
// ---------------------------------------------------------------------------
#define INV_TAU (1.0f / 0.07f)
static constexpr int D_DIM   = 256;     // GEMM K
static constexpr int NZ      = 512;     // B*L frames
static constexpr int NITEMS  = 1028;    // 1024 queue chunks (128 rows) + 4 z chunks
static constexpr int NQITEMS = 1024;
static constexpr int MTILES  = 9;       // 8 x 64 z-rows + 1 x (16 g rows + pad)
static constexpr int MREAL   = 528;     // 512 z + 16 g
static constexpr int GRID    = 148;
static constexpr int SMEM_BYTES = 2 * 32768 + 2 * 65536;   // A bufs + B bufs = 192KB

// ---------------------------------------------------------------------------
// Scratch (device globals; allocation-free)
// ---------------------------------------------------------------------------
__device__ __nv_bfloat16 g_A[640 * 256];        // pre-swizzled A (z/tau, g/tau, pad)
__device__ float g_pmax[(size_t)NQITEMS * MREAL];
__device__ float g_psum[(size_t)NQITEMS * MREAL];
__device__ float g_logits[(size_t)MREAL * NZ];  // fp32 logits vs z columns
__device__ float g_lse[MREAL];
__device__ float g_cll[NZ];
__device__ float g_csm[NZ];
__device__ float g_cgl[16];

#define DEV_INLINE __device__ __forceinline__

DEV_INLINE uint32_t smem_u32(const void* p) {
    uint32_t a;
    asm("{ .reg .u64 t; cvta.to.shared.u64 t, %1; cvt.u32.u64 %0, t; }" : "=r"(a) : "l"(p));
    return a;
}
DEV_INLINE void ldsm_x4(uint32_t* r, uint32_t addr) {
    asm volatile("ldmatrix.sync.aligned.m8n8.x4.shared.b16 {%0,%1,%2,%3}, [%4];"
                 : "=r"(r[0]), "=r"(r[1]), "=r"(r[2]), "=r"(r[3]) : "r"(addr));
}
DEV_INLINE void mma16816(float* d, const uint32_t* a, uint32_t b0, uint32_t b1) {
    asm volatile(
        "mma.sync.aligned.m16n8k16.row.col.f32.bf16.bf16.f32 "
        "{%0,%1,%2,%3}, {%4,%5,%6,%7}, {%8,%9}, {%0,%1,%2,%3};"
        : "+f"(d[0]), "+f"(d[1]), "+f"(d[2]), "+f"(d[3])
        : "r"(a[0]), "r"(a[1]), "r"(a[2]), "r"(a[3]), "r"(b0), "r"(b1));
}
DEV_INLINE void cp_async16(uint32_t dst, const void* src) {
    asm volatile("cp.async.cg.shared.global [%0], [%1], 16;" :: "r"(dst), "l"(src) : "memory");
}
DEV_INLINE void cp_commit() { asm volatile("cp.async.commit_group;" ::: "memory"); }
DEV_INLINE void cp_wait1()  { asm volatile("cp.async.wait_group 1;" ::: "memory"); }

DEV_INLINE void lse_acc(float& m, float& s, float m2, float s2) {
    if (m2 == -INFINITY) return;
    if (m2 <= m) {
        s += s2 * __expf(m2 - m);
    } else {
        s = s * __expf(m - m2) + s2;
        m = m2;
    }
}
DEV_INLINE float logaddexp_f(float a, float b) {
    float mx = fmaxf(a, b);
    return mx + log1pf(__expf(-fabsf(a - b)));
}

// ---------------------------------------------------------------------------
// Kernel 1: build A (bf16, scaled 1/tau, XOR-swizzled 512B rows)
//   byte = row*512 + ((c/8 ^ (row&7))*16) + (c%8)*2
// ---------------------------------------------------------------------------
__global__ void prep_kernel(const float* __restrict__ zt, const float* __restrict__ gv) {
    int row = blockIdx.x;    // 0..639
    int c   = threadIdx.x;   // 0..255
    float v = 0.f;
    if (row < NZ)            v = zt[row * D_DIM + c] * INV_TAU;
    else if (row < NZ + 16)  v = gv[(row - NZ) * D_DIM + c] * INV_TAU;
    uint32_t off = (uint32_t)row * 512u
                 + ((((uint32_t)c >> 3) ^ ((uint32_t)row & 7u)) << 4)
                 + ((uint32_t)c & 7u) * 2u;
    *(__nv_bfloat16*)((char*)g_A + off) = __float2bfloat16_rn(v);
}

// ---------------------------------------------------------------------------
// Kernel 2: persistent pipelined bf16 mma.sync GEMM + fused LSE / logits
//   148 CTAs x 512 threads (16 warps, 4x4 grid, 32x32 warp tiles)
//   item < 1024: queue chunk (128 rows) -> (max,sumexp) partials per row
//   item >= 1024: z chunk -> fp32 logits dump
//   Pipelines: A tiles double-buffered via cp.async; next item's B chunk
//   converted fp32->bf16 spread across current item's 9 M-tile iterations.
// ---------------------------------------------------------------------------
__global__ void __launch_bounds__(512, 1)
gemm_kernel(const float* __restrict__ mq, const float* __restrict__ zt) {
    extern __shared__ __align__(16) char smem[];
    __shared__ float spm[64][4];
    __shared__ float sps[64][4];

    const int tid = threadIdx.x;
    const int l   = tid & 31;
    const int w   = tid >> 5;
    const int wr  = w >> 2;            // 0..3 -> rows wr*16
    const int wc  = w & 3;             // 0..3 -> cols wc*32

    const uint32_t sbase = smem_u32(smem);
    const uint32_t sA0 = sbase;              // A bufs: 2 x 32KB at +0, +32K
    const uint32_t sB0 = sbase + 65536;      // B bufs: 2 x 64KB at +64K, +128K
    const char* gAb = (const char*)g_A;

    // lane-invariant ldmatrix row bases / k-octet selectors
    const uint32_t arow  = (uint32_t)(wr * 16 + (l & 7) + 8 * ((l >> 3) & 1));
    const uint32_t brow0 = (uint32_t)(wc * 32 + (l & 7) + 8 * (l >> 4));
    const uint32_t brow1 = brow0 + 16;
    const uint32_t asel  = (uint32_t)(l >> 4);
    const uint32_t bsel  = (uint32_t)((l >> 3) & 1);
    const uint32_t lsw   = (uint32_t)(l & 7);

    const int grid = gridDim.x;
    const int bid  = blockIdx.x;

    // ---- prologue: fill Bbuf0 for first item; prefetch A tile 0 ----
    {
        const float4* src = (bid < NQITEMS)
            ? ((const float4*)mq + (size_t)bid * 8192)
            : ((const float4*)zt + (size_t)(bid - NQITEMS) * 8192);
        char* pB = smem + 65536;
#pragma unroll
        for (int k = 0; k < 8; k++) {
            int i  = tid + k * 512;
            int r  = i >> 5, c4 = i & 31;
            float4 f0 = src[r * 64 + c4 * 2];
            float4 f1 = src[r * 64 + c4 * 2 + 1];
            __nv_bfloat162 p0 = __floats2bfloat162_rn(f0.x, f0.y);
            __nv_bfloat162 p1 = __floats2bfloat162_rn(f0.z, f0.w);
            __nv_bfloat162 p2 = __floats2bfloat162_rn(f1.x, f1.y);
            __nv_bfloat162 p3 = __floats2bfloat162_rn(f1.z, f1.w);
            uint4 v;
            v.x = *reinterpret_cast<uint32_t*>(&p0);
            v.y = *reinterpret_cast<uint32_t*>(&p1);
            v.z = *reinterpret_cast<uint32_t*>(&p2);
            v.w = *reinterpret_cast<uint32_t*>(&p3);
            *(uint4*)(pB + (uint32_t)r * 512u + ((((uint32_t)c4 ^ ((uint32_t)r & 7u))) << 4)) = v;
        }
#pragma unroll
        for (int k = 0; k < 4; k++) {
            int g = tid + k * 512;
            cp_async16(sA0 + (uint32_t)g * 16u, gAb + g * 16);
        }
        cp_commit();
    }

    int gt = 0;        // global tile counter -> A buffer parity
    int bpar = 0;      // B buffer parity

    for (int item = bid; item < NITEMS; item += grid) {
        const bool isq = (item < NQITEMS);
        int nxt = item + grid;
        if (nxt >= NITEMS) nxt = item;     // clamp: harmless re-read, buffer unused
        const float4* nsrc = (nxt < NQITEMS)
            ? ((const float4*)mq + (size_t)nxt * 8192)
            : ((const float4*)zt + (size_t)(nxt - NQITEMS) * 8192);
        char* pBn = smem + 65536 + ((bpar ^ 1) << 16);

        for (int mt = 0; mt < MTILES; mt++) {
            __syncthreads();   // prior tile SMEM reads + spm reads complete

            // prefetch next A tile into the other A buffer
            {
                int ntile = (mt == 8) ? 0 : (mt + 1);
                uint32_t adst = sA0 + (uint32_t)((~gt & 1) << 15);
                const char* asrc = gAb + (size_t)ntile * 32768;
#pragma unroll
                for (int k = 0; k < 4; k++) {
                    int g = tid + k * 512;
                    cp_async16(adst + (uint32_t)g * 16u, asrc + g * 16);
                }
                cp_commit();
            }

            // issue next-B conversion loads (latency hides under MMA)
            float4 f0, f1; int cr = 0, cc4 = 0;
            if (mt < 8) {
                int ci = tid + (mt << 9);
                cr = ci >> 5; cc4 = ci & 31;
                f0 = nsrc[cr * 64 + cc4 * 2];
                f1 = nsrc[cr * 64 + cc4 * 2 + 1];
            }

            cp_wait1();        // current A tile (committed last iter) complete
            __syncthreads();   // visible to all warps

            // ---- MMA: 32x32 warp tile, K=256 in 16 steps ----
            float d[4][4];
#pragma unroll
            for (int nf = 0; nf < 4; nf++)
#pragma unroll
                for (int v = 0; v < 4; v++) d[nf][v] = 0.f;

            const uint32_t abase  = sA0 + (uint32_t)((gt & 1) << 15) + arow * 512u;
            const uint32_t bb     = sB0 + (uint32_t)(bpar << 16);
            const uint32_t bbase0 = bb + brow0 * 512u;
            const uint32_t bbase1 = bb + brow1 * 512u;
#pragma unroll
            for (int ks = 0; ks < 16; ks++) {
                uint32_t a[4], b0[4], b1[4];
                uint32_t offA = (((uint32_t)(2 * ks) + asel) ^ lsw) << 4;
                uint32_t offB = (((uint32_t)(2 * ks) + bsel) ^ lsw) << 4;
                ldsm_x4(a,  abase  + offA);
                ldsm_x4(b0, bbase0 + offB);
                ldsm_x4(b1, bbase1 + offB);
                mma16816(d[0], a, b0[0], b0[1]);
                mma16816(d[1], a, b0[2], b0[3]);
                mma16816(d[2], a, b1[0], b1[1]);
                mma16816(d[3], a, b1[2], b1[3]);
            }

            // store converted next-B into the other B buffer
            if (mt < 8) {
                __nv_bfloat162 p0 = __floats2bfloat162_rn(f0.x, f0.y);
                __nv_bfloat162 p1 = __floats2bfloat162_rn(f0.z, f0.w);
                __nv_bfloat162 p2 = __floats2bfloat162_rn(f1.x, f1.y);
                __nv_bfloat162 p3 = __floats2bfloat162_rn(f1.z, f1.w);
                uint4 v;
                v.x = *reinterpret_cast<uint32_t*>(&p0);
                v.y = *reinterpret_cast<uint32_t*>(&p1);
                v.z = *reinterpret_cast<uint32_t*>(&p2);
                v.w = *reinterpret_cast<uint32_t*>(&p3);
                *(uint4*)(pBn + (uint32_t)cr * 512u + ((((uint32_t)cc4 ^ ((uint32_t)cr & 7u))) << 4)) = v;
            }

            // ---- epilogue ----
            if (isq) {
                // rows r0 = wr*16 + (l>>2), r1 = r0+8; 8 cols per row-slot
                float m0 = -INFINITY, m1 = -INFINITY;
#pragma unroll
                for (int nf = 0; nf < 4; nf++) {
                    m0 = fmaxf(m0, fmaxf(d[nf][0], d[nf][1]));
                    m1 = fmaxf(m1, fmaxf(d[nf][2], d[nf][3]));
                }
                m0 = fmaxf(m0, __shfl_xor_sync(0xffffffffu, m0, 1));
                m0 = fmaxf(m0, __shfl_xor_sync(0xffffffffu, m0, 2));
                m1 = fmaxf(m1, __shfl_xor_sync(0xffffffffu, m1, 1));
                m1 = fmaxf(m1, __shfl_xor_sync(0xffffffffu, m1, 2));
                float s0 = 0.f, s1 = 0.f;
#pragma unroll
                for (int nf = 0; nf < 4; nf++) {
                    float t0 = d[nf][0] - m0; if (t0 > -20.f) s0 += __expf(t0);
                    float t1 = d[nf][1] - m0; if (t1 > -20.f) s0 += __expf(t1);
                    float t2 = d[nf][2] - m1; if (t2 > -20.f) s1 += __expf(t2);
                    float t3 = d[nf][3] - m1; if (t3 > -20.f) s1 += __expf(t3);
                }
                s0 += __shfl_xor_sync(0xffffffffu, s0, 1);
                s0 += __shfl_xor_sync(0xffffffffu, s0, 2);
                s1 += __shfl_xor_sync(0xffffffffu, s1, 1);
                s1 += __shfl_xor_sync(0xffffffffu, s1, 2);
                if ((l & 3) == 0) {
                    int rr = wr * 16 + (l >> 2);
                    spm[rr][wc] = m0;      sps[rr][wc] = s0;
                    spm[rr + 8][wc] = m1;  sps[rr + 8][wc] = s1;
                }
                __syncthreads();
                int lim = (mt == 8) ? 16 : 64;     // tile 8: only 16 real g rows
                if (tid < lim) {
                    float m = spm[tid][0], s = sps[tid][0];
                    lse_acc(m, s, spm[tid][1], sps[tid][1]);
                    lse_acc(m, s, spm[tid][2], sps[tid][2]);
                    lse_acc(m, s, spm[tid][3], sps[tid][3]);
                    g_pmax[(size_t)item * MREAL + mt * 64 + tid] = m;
                    g_psum[(size_t)item * MREAL + mt * 64 + tid] = s;
                }
            } else {
                if (mt < 8 || wr == 0) {
                    int zi   = item - NQITEMS;
                    int grow = mt * 64 + wr * 16 + (l >> 2);
                    int col  = zi * 128 + wc * 32 + 2 * (l & 3);
#pragma unroll
                    for (int nf = 0; nf < 4; nf++) {
                        *(float2*)&g_logits[(size_t)grow * NZ + col + nf * 8] =
                            make_float2(d[nf][0], d[nf][1]);
                        *(float2*)&g_logits[(size_t)(grow + 8) * NZ + col + nf * 8] =
                            make_float2(d[nf][2], d[nf][3]);
                    }
                }
            }
            gt++;
        }
        bpar ^= 1;
    }
}

// ---------------------------------------------------------------------------
// Kernel 3: combine 1024 chunk partials per row -> queue LSE
// ---------------------------------------------------------------------------
__global__ void reduce_kernel() {
    int row = blockIdx.x;      // 0..527
    int tid = threadIdx.x;     // 128
    float m = -INFINITY, s = 0.f;
    for (int c = tid; c < NQITEMS; c += 128)
        lse_acc(m, s, g_pmax[(size_t)c * MREAL + row], g_psum[(size_t)c * MREAL + row]);
    __shared__ float shm[128], shs[128];
    shm[tid] = m; shs[tid] = s;
    for (int off = 64; off; off >>= 1) {
        __syncthreads();
        if (tid < off) {
            float m1 = shm[tid], s1 = shs[tid];
            lse_acc(m1, s1, shm[tid + off], shs[tid + off]);
            shm[tid] = m1; shs[tid] = s1;
        }
    }
    if (tid == 0) g_lse[row] = shm[0] + logf(shs[0]);
}

// ---------------------------------------------------------------------------
// Kernel 4: masked LSE vs z-columns + combine + pos terms + smoothness
// ---------------------------------------------------------------------------
__global__ void final_kernel(const float* __restrict__ zt) {
    __shared__ float shm[256], shs[256];
    __shared__ float s_lneg;
    int r = blockIdx.x, tid = threadIdx.x;

    if (r < NZ) {
        int t = r & 31;
        const float* lrow = g_logits + (size_t)r * NZ;
        if (t != 31) {   // local-local anchor
            int c0 = tid, c1 = tid + 256;
            float v0 = lrow[c0]; if (c0 == r || c0 == r + 1) v0 = -INFINITY;
            float v1 = lrow[c1]; if (c1 == r || c1 == r + 1) v1 = -INFINITY;
            float m = -INFINITY, s = 0.f;
            lse_acc(m, s, v0, 1.f);
            lse_acc(m, s, v1, 1.f);
            shm[tid] = m; shs[tid] = s;
            for (int off = 128; off; off >>= 1) {
                __syncthreads();
                if (tid < off) {
                    float m1 = shm[tid], s1 = shs[tid];
                    lse_acc(m1, s1, shm[tid + off], shs[tid + off]);
                    shm[tid] = m1; shs[tid] = s1;
                }
            }
            if (tid == 0) {
                float lse_z   = shm[0] + logf(shs[0]);
                float lse_all = logaddexp_f(lse_z, g_lse[r]);
                float pos = lrow[r + 1];
                g_cll[r] = logaddexp_f(pos, lse_all) - pos;
            }
        } else if (tid == 0) {
            g_cll[r] = 0.f;
        }
        __syncthreads();
        if (t != 0) {   // smoothness ||z[r]-z[r-1]||^2
            float dd = zt[r * D_DIM + tid] - zt[(r - 1) * D_DIM + tid];
            shs[tid] = dd * dd;
            for (int off = 128; off; off >>= 1) {
                __syncthreads();
                if (tid < off) shs[tid] += shs[tid + off];
            }
            if (tid == 0) g_csm[r] = shs[0];
        } else if (tid == 0) {
            g_csm[r] = 0.f;
        }
    } else {             // global-local row for batch b
        int b = r - NZ;
        const float* lrow = g_logits + (size_t)r * NZ;
        int c0 = tid, c1 = tid + 256;
        float v0 = lrow[c0]; if ((c0 >> 5) == b) v0 = -INFINITY;
        float v1 = lrow[c1]; if ((c1 >> 5) == b) v1 = -INFINITY;
        float m = -INFINITY, s = 0.f;
        lse_acc(m, s, v0, 1.f);
        lse_acc(m, s, v1, 1.f);
        shm[tid] = m; shs[tid] = s;
        for (int off = 128; off; off >>= 1) {
            __syncthreads();
            if (tid < off) {
                float m1 = shm[tid], s1 = shs[tid];
                lse_acc(m1, s1, shm[tid + off], shs[tid + off]);
                shm[tid] = m1; shs[tid] = s1;
            }
        }
        if (tid == 0) s_lneg = logaddexp_f(shm[0] + logf(shs[0]), g_lse[r]);
        __syncthreads();
        if (tid < 32) {
            float pos = lrow[b * 32 + tid];
            float c = logaddexp_f(pos, s_lneg) - pos;
            for (int o = 16; o; o >>= 1) c += __shfl_down_sync(0xffffffffu, c, o);
            if (tid == 0) g_cgl[b] = c;
        }
    }
}

// ---------------------------------------------------------------------------
// Kernel 5: deterministic weighted sum -> d_out[0]
// ---------------------------------------------------------------------------
__global__ void sum_kernel(float* __restrict__ out) {
    __shared__ float sh[256];
    int tid = threadIdx.x;
    float a = 0.f;
    for (int i = tid; i < NZ; i += 256)
        a += g_cll[i] * (1.0f / 496.0f) + g_csm[i] * (0.1f / 496.0f);
    if (tid < 16) a += g_cgl[tid] * (0.5f / 512.0f);
    sh[tid] = a;
    for (int off = 128; off; off >>= 1) {
        __syncthreads();
        if (tid < off) sh[tid] += sh[tid + off];
    }
    if (tid == 0) out[0] = sh[0];
}

// ---------------------------------------------------------------------------
// Launch
// ---------------------------------------------------------------------------
extern "C" void kernel_launch(void* const* d_in, const int* in_sizes, int n_in,
                              void* d_out, int out_size) {
    (void)in_sizes; (void)n_in; (void)out_size;
    const float* zt = (const float*)d_in[0];   // [16,32,256]
    const float* gv = (const float*)d_in[1];   // [16,256]
    const float* mq = (const float*)d_in[3];   // [131072,256]

    cudaFuncSetAttribute((const void*)gemm_kernel,
                         cudaFuncAttributeMaxDynamicSharedMemorySize, SMEM_BYTES);

    prep_kernel<<<640, 256>>>(zt, gv);
    gemm_kernel<<<GRID, 512, SMEM_BYTES>>>(mq, zt);
    reduce_kernel<<<528, 128>>>();
    final_kernel<<<528, 256>>>(zt);
    sum_kernel<<<1, 256>>>((float*)d_out);
}